// round 3
// baseline (speedup 1.0000x reference)
#include <cuda_runtime.h>
#include <cuda_bf16.h>
#include <cstddef>

// Problem shape (fixed by the reference setup_inputs): B=4, L=256, H=256.
#define PB 4
#define PL 256
#define PH 256
#define IG 8            // i-values per block (register-held c_pad vectors)
#define H4 (PH / 4)     // 64 float4 lanes per row
#define JQ (PL / 4)     // j-quarter length = 64

// Scratch for the cumsum: 4*256*256 floats = 1 MB. Static device global (no alloc).
__device__ float g_cumsum[PB * PL * PH];

// ---------------------------------------------------------------------------
// Kernel 1: per-(b,h) cumulative sum along L.
// grid = 8 blocks x 128 threads = 1024 lanes, one per (b,h) column.
// Loads/stores coalesced across the 128 consecutive h of each block (h-major).
// Serial FADD chain of 256 per lane; loads are chain-independent so the
// compiler prefetches ahead under the unroll.
// ---------------------------------------------------------------------------
__global__ __launch_bounds__(128) void cumsum_kernel(const float* __restrict__ in) {
    const int lane = blockIdx.x * 128 + threadIdx.x;   // 0..1023
    const int b = lane >> 8;          // 0..3
    const int h = lane & (PH - 1);    // 0..255
    const float* p = in + (size_t)b * PL * PH + h;
    float* q = g_cumsum + (size_t)b * PL * PH + h;
    float acc = 0.0f;
#pragma unroll 8
    for (int l = 0; l < PL; ++l) {
        acc += p[(size_t)l * PH];
        q[(size_t)l * PH] = acc;
    }
}

// ---------------------------------------------------------------------------
// Kernel 2: out[b,i,j,h] = (c[b,j,h] - c_pad[b,i,h]) * (1/(|i-j|+1))
//
// Block: 256 threads. tid -> (jj = tid>>6 in 0..3, h4 = tid&63).
// Block handles (b, 8 consecutive i's, one quarter of the j range).
// Each thread registers 8 c_pad float4's (one per i), then streams c[b,j,h4]
// once per j and fans it out to 8 output rows -> 8x reduction in c-read
// traffic. Stores are float4, coalesced, streaming (__stcs) so the one-shot
// 256 MB output stream doesn't evict the hot cumsum lines from L2.
// ---------------------------------------------------------------------------
__global__ __launch_bounds__(256) void span_mean_kernel(float* __restrict__ out) {
    __shared__ float s_inv[PL];

    const int tid = threadIdx.x;
    if (tid < PL) s_inv[tid] = 1.0f / (float)(tid + 1);

    const int h4 = tid & (H4 - 1);   // 0..63
    const int jj = tid >> 6;         // 0..3
    const int i0 = blockIdx.x * IG;  // 0,8,...,248
    const int b  = blockIdx.y;       // 0..3
    const int jbase = blockIdx.z * JQ;  // 0,64,128,192

    __syncthreads();

    const float4* __restrict__ c4 = (const float4*)(g_cumsum + (size_t)b * PL * PH);

    // Register-resident c_pad for the 8 i's this block owns.
    float4 cp[IG];
#pragma unroll
    for (int k = 0; k < IG; ++k) {
        const int i = i0 + k;
        cp[k] = (i == 0) ? make_float4(0.f, 0.f, 0.f, 0.f)
                         : c4[(size_t)(i - 1) * H4 + h4];
    }

    // Output base for (b, i0, j=0, h4).
    float4* __restrict__ o4 =
        (float4*)out + ((size_t)b * PL + i0) * PL * H4 + h4;

#pragma unroll 4
    for (int j = jbase + jj; j < jbase + JQ; j += 4) {
        const float4 cj = c4[(size_t)j * H4 + h4];
#pragma unroll
        for (int k = 0; k < IG; ++k) {
            const int i = i0 + k;
            const float inv = s_inv[abs(i - j)];
            float4 v;
            v.x = (cj.x - cp[k].x) * inv;
            v.y = (cj.y - cp[k].y) * inv;
            v.z = (cj.z - cp[k].z) * inv;
            v.w = (cj.w - cp[k].w) * inv;
            __stcs(&o4[((size_t)k * PL + j) * H4], v);
        }
    }
}

// ---------------------------------------------------------------------------
extern "C" void kernel_launch(void* const* d_in, const int* in_sizes, int n_in,
                              void* d_out, int out_size) {
    const float* seq = (const float*)d_in[0];
    float* out = (float*)d_out;

    cumsum_kernel<<<8, 128>>>(seq);

    dim3 grid(PL / IG, PB, 4);   // (32, 4, 4) = 512 blocks
    span_mean_kernel<<<grid, 256>>>(out);
}

// round 4
// speedup vs baseline: 1.2218x; 1.2218x over previous
#include <cuda_runtime.h>
#include <cuda_bf16.h>
#include <cstddef>

// Problem shape (fixed by the reference setup_inputs): B=4, L=256, H=256.
#define PB 4
#define PL 256
#define PH 256
#define IG 4            // i-values per block (register-held c_pad vectors)
#define H4 (PH / 4)     // 64 float4 lanes per row
#define JQ (PL / 4)     // j-quarter length = 64
#define LCHUNK 32       // L-elements per thread in the cumsum scan

// Scratch for the cumsum: 4*256*256 floats = 1 MB. Static device global (no alloc).
__device__ float g_cumsum[PB * PL * PH];

// ---------------------------------------------------------------------------
// Kernel 1: per-(b,h) cumulative sum along L — two-phase block scan.
// grid = (PB, PH/32) = 32 blocks, block = 256 threads = 8 L-chunks x 32 h.
// Phase 1: each thread loads its 32 L-elements (independent -> high MLP,
//          kept in registers) and computes the chunk sum.
// Phase 2: smem exchange of the 8 chunk sums per h; each thread sums the
//          chunks below it to get its exclusive offset.
// Phase 3: replay from registers, writing offset + running prefix.
// ---------------------------------------------------------------------------
__global__ __launch_bounds__(256) void cumsum_kernel(const float* __restrict__ in) {
    __shared__ float s_csum[8 * 32];   // [lc][hw]

    const int tid = threadIdx.x;
    const int hw  = tid & 31;          // 0..31
    const int lc  = tid >> 5;          // 0..7
    const int b   = blockIdx.x;        // 0..3
    const int h   = blockIdx.y * 32 + hw;

    const float* p = in + ((size_t)b * PL + (size_t)lc * LCHUNK) * PH + h;
    float* q = g_cumsum + ((size_t)b * PL + (size_t)lc * LCHUNK) * PH + h;

    float vals[LCHUNK];
    float csum = 0.0f;
#pragma unroll
    for (int t = 0; t < LCHUNK; ++t) {
        vals[t] = p[(size_t)t * PH];
        csum += vals[t];
    }
    s_csum[lc * 32 + hw] = csum;
    __syncthreads();

    float offset = 0.0f;
#pragma unroll
    for (int q2 = 0; q2 < 7; ++q2)
        if (q2 < lc) offset += s_csum[q2 * 32 + hw];

    float acc = offset;
#pragma unroll
    for (int t = 0; t < LCHUNK; ++t) {
        acc += vals[t];
        q[(size_t)t * PH] = acc;
    }
}

// ---------------------------------------------------------------------------
// Kernel 2: out[b,i,j,h] = (c[b,j,h] - c_pad[b,i,h]) * (1/(|i-j|+1))
//
// Block: 256 threads. tid -> (jj = tid>>6 in 0..3, h4 = tid&63).
// Block handles (b, 4 consecutive i's, one quarter of the j range).
// Each thread registers 4 c_pad float4's (one per i), then streams c[b,j,h4]
// once per j and fans it out to 4 output rows. Stores are float4, coalesced,
// streaming (__stcs) so the one-shot 256 MB output stream doesn't evict the
// hot cumsum lines from L2.
// grid = (64, 4, 4) = 1024 blocks; regs capped for >=6 blocks/SM residency.
// ---------------------------------------------------------------------------
__global__ __launch_bounds__(256, 6) void span_mean_kernel(float* __restrict__ out) {
    __shared__ float s_inv[PL];

    const int tid = threadIdx.x;
    if (tid < PL) s_inv[tid] = 1.0f / (float)(tid + 1);

    const int h4 = tid & (H4 - 1);   // 0..63
    const int jj = tid >> 6;         // 0..3
    const int i0 = blockIdx.x * IG;  // 0,4,...,252
    const int b  = blockIdx.y;       // 0..3
    const int jbase = blockIdx.z * JQ;  // 0,64,128,192

    __syncthreads();

    const float4* __restrict__ c4 = (const float4*)(g_cumsum + (size_t)b * PL * PH);

    // Register-resident c_pad for the 4 i's this block owns.
    float4 cp[IG];
#pragma unroll
    for (int k = 0; k < IG; ++k) {
        const int i = i0 + k;
        cp[k] = (i == 0) ? make_float4(0.f, 0.f, 0.f, 0.f)
                         : c4[(size_t)(i - 1) * H4 + h4];
    }

    // Output base for (b, i0, j=0, h4).
    float4* __restrict__ o4 =
        (float4*)out + ((size_t)b * PL + i0) * PL * H4 + h4;

#pragma unroll 4
    for (int j = jbase + jj; j < jbase + JQ; j += 4) {
        const float4 cj = c4[(size_t)j * H4 + h4];
#pragma unroll
        for (int k = 0; k < IG; ++k) {
            const int i = i0 + k;
            const float inv = s_inv[abs(i - j)];
            float4 v;
            v.x = (cj.x - cp[k].x) * inv;
            v.y = (cj.y - cp[k].y) * inv;
            v.z = (cj.z - cp[k].z) * inv;
            v.w = (cj.w - cp[k].w) * inv;
            __stcs(&o4[((size_t)k * PL + j) * H4], v);
        }
    }
}

// ---------------------------------------------------------------------------
extern "C" void kernel_launch(void* const* d_in, const int* in_sizes, int n_in,
                              void* d_out, int out_size) {
    const float* seq = (const float*)d_in[0];
    float* out = (float*)d_out;

    dim3 cgrid(PB, PH / 32);
    cumsum_kernel<<<cgrid, 256>>>(seq);

    dim3 grid(PL / IG, PB, 4);   // (64, 4, 4) = 1024 blocks
    span_mean_kernel<<<grid, 256>>>(out);
}

// round 5
// speedup vs baseline: 1.2859x; 1.0525x over previous
#include <cuda_runtime.h>
#include <cuda_bf16.h>
#include <cstddef>

// Problem shape (fixed by the reference setup_inputs): B=4, L=256, H=256.
#define PB 4
#define PL 256
#define PH 256
#define IG 2            // i-values per block (register-held c_pad vectors)
#define H4 (PH / 4)     // 64 float4 lanes per row
#define JQ (PL / 4)     // j-quarter length = 64
#define LCHUNK 8        // L-elements per thread in the cumsum scan

// Scratch for the cumsum: 4*256*256 floats = 1 MB. Static device global (no alloc).
__device__ float g_cumsum[PB * PL * PH];

// ---------------------------------------------------------------------------
// Kernel 1: per-(b,h) cumulative sum along L — two-phase block scan.
// grid = (PB, PH/8) = 128 blocks, block = 256 threads = 32 L-chunks x 8 h.
// Phase 1: each thread loads its 8 L-elements (independent -> high MLP,
//          kept in registers) and computes the chunk sum.
// Phase 2: smem exchange of the 32 chunk sums per h; each thread sums the
//          chunks below it to get its exclusive offset.
// Phase 3: replay from registers, writing offset + running prefix.
// ---------------------------------------------------------------------------
__global__ __launch_bounds__(256) void cumsum_kernel(const float* __restrict__ in) {
    __shared__ float s_csum[32 * 8];   // [lc][hw]

    const int tid = threadIdx.x;
    const int hw  = tid & 7;           // 0..7
    const int lc  = tid >> 3;          // 0..31
    const int b   = blockIdx.x;        // 0..3
    const int h   = blockIdx.y * 8 + hw;

    const float* p = in + ((size_t)b * PL + (size_t)lc * LCHUNK) * PH + h;
    float* q = g_cumsum + ((size_t)b * PL + (size_t)lc * LCHUNK) * PH + h;

    float vals[LCHUNK];
    float csum = 0.0f;
#pragma unroll
    for (int t = 0; t < LCHUNK; ++t) {
        vals[t] = p[(size_t)t * PH];
        csum += vals[t];
    }
    s_csum[lc * 8 + hw] = csum;
    __syncthreads();

    float offset = 0.0f;
#pragma unroll
    for (int q2 = 0; q2 < 31; ++q2)
        if (q2 < lc) offset += s_csum[q2 * 8 + hw];

    float acc = offset;
#pragma unroll
    for (int t = 0; t < LCHUNK; ++t) {
        acc += vals[t];
        q[(size_t)t * PH] = acc;
    }
}

// ---------------------------------------------------------------------------
// Kernel 2: out[b,i,j,h] = (c[b,j,h] - c_pad[b,i,h]) * (1/(|i-j|+1))
//
// Block: 256 threads. tid -> (jj = tid>>6 in 0..3, h4 = tid&63).
// Block handles (b, 2 consecutive i's, one quarter of the j range).
// Each thread registers 2 c_pad float4's (one per i), then streams c[b,j,h4]
// once per j and fans it out to 2 output rows. Stores are float4, coalesced,
// streaming (__stcs) so the one-shot 256 MB output stream doesn't evict the
// hot cumsum lines from L2.
// grid = (128, 4, 4) = 2048 blocks; regs capped for 7 blocks/SM (87.5% occ).
// ---------------------------------------------------------------------------
__global__ __launch_bounds__(256, 7) void span_mean_kernel(float* __restrict__ out) {
    __shared__ float s_inv[PL];

    const int tid = threadIdx.x;
    if (tid < PL) s_inv[tid] = 1.0f / (float)(tid + 1);

    const int h4 = tid & (H4 - 1);   // 0..63
    const int jj = tid >> 6;         // 0..3
    const int i0 = blockIdx.x * IG;  // 0,2,...,254
    const int b  = blockIdx.y;       // 0..3
    const int jbase = blockIdx.z * JQ;  // 0,64,128,192

    __syncthreads();

    const float4* __restrict__ c4 = (const float4*)(g_cumsum + (size_t)b * PL * PH);

    // Register-resident c_pad for the 2 i's this block owns.
    float4 cp[IG];
#pragma unroll
    for (int k = 0; k < IG; ++k) {
        const int i = i0 + k;
        cp[k] = (i == 0) ? make_float4(0.f, 0.f, 0.f, 0.f)
                         : c4[(size_t)(i - 1) * H4 + h4];
    }

    // Output base for (b, i0, j=0, h4).
    float4* __restrict__ o4 =
        (float4*)out + ((size_t)b * PL + i0) * PL * H4 + h4;

#pragma unroll 4
    for (int j = jbase + jj; j < jbase + JQ; j += 4) {
        const float4 cj = c4[(size_t)j * H4 + h4];
#pragma unroll
        for (int k = 0; k < IG; ++k) {
            const int i = i0 + k;
            const float inv = s_inv[abs(i - j)];
            float4 v;
            v.x = (cj.x - cp[k].x) * inv;
            v.y = (cj.y - cp[k].y) * inv;
            v.z = (cj.z - cp[k].z) * inv;
            v.w = (cj.w - cp[k].w) * inv;
            __stcs(&o4[((size_t)k * PL + j) * H4], v);
        }
    }
}

// ---------------------------------------------------------------------------
extern "C" void kernel_launch(void* const* d_in, const int* in_sizes, int n_in,
                              void* d_out, int out_size) {
    const float* seq = (const float*)d_in[0];
    float* out = (float*)d_out;

    dim3 cgrid(PB, PH / 8);
    cumsum_kernel<<<cgrid, 256>>>(seq);

    dim3 grid(PL / IG, PB, 4);   // (128, 4, 4) = 2048 blocks
    span_mean_kernel<<<grid, 256>>>(out);
}

// round 6
// speedup vs baseline: 1.3227x; 1.0286x over previous
#include <cuda_runtime.h>
#include <cuda_bf16.h>
#include <cstddef>

// Problem shape (fixed by the reference setup_inputs): B=4, L=256, H=256.
#define PB 4
#define PL 256
#define PH 256
#define IG 2            // i-values per block (register-held c_pad vectors)
#define H4 (PH / 4)     // 64 float4 lanes per row
#define JQ (PL / 4)     // j-quarter length = 64
#define LCHUNK 8        // L-elements per thread in the cumsum scan

// Scratch for the cumsum: 4*256*256 floats = 1 MB. Static device global (no alloc).
__device__ float g_cumsum[PB * PL * PH];

// ---------------------------------------------------------------------------
// Kernel 1: per-(b,h) cumulative sum along L — two-phase block scan.
// grid = (PB, PH/8) = 128 blocks, block = 256 threads = 32 L-chunks x 8 h.
// Triggers the dependent span kernel immediately (PDL): span's launch +
// prologue overlap this kernel; span's grid-dependency-sync provides the
// ordering on g_cumsum.
// ---------------------------------------------------------------------------
__global__ __launch_bounds__(256) void cumsum_kernel(const float* __restrict__ in) {
    cudaTriggerProgrammaticLaunchCompletion();

    __shared__ float s_csum[32 * 8];   // [lc][hw]

    const int tid = threadIdx.x;
    const int hw  = tid & 7;           // 0..7
    const int lc  = tid >> 3;          // 0..31
    const int b   = blockIdx.x;        // 0..3
    const int h   = blockIdx.y * 8 + hw;

    const float* p = in + ((size_t)b * PL + (size_t)lc * LCHUNK) * PH + h;
    float* q = g_cumsum + ((size_t)b * PL + (size_t)lc * LCHUNK) * PH + h;

    float vals[LCHUNK];
    float csum = 0.0f;
#pragma unroll
    for (int t = 0; t < LCHUNK; ++t) {
        vals[t] = p[(size_t)t * PH];
        csum += vals[t];
    }
    s_csum[lc * 8 + hw] = csum;
    __syncthreads();

    float offset = 0.0f;
#pragma unroll
    for (int q2 = 0; q2 < 31; ++q2)
        if (q2 < lc) offset += s_csum[q2 * 8 + hw];

    float acc = offset;
#pragma unroll
    for (int t = 0; t < LCHUNK; ++t) {
        acc += vals[t];
        q[(size_t)t * PH] = acc;
    }
}

// ---------------------------------------------------------------------------
// Kernel 2: out[b,i,j,h] = (c[b,j,h] - c_pad[b,i,h]) * (1/(|i-j|+1))
//
// At the measured DRAM write-drain wall (~4.7 TB/s effective): do not disturb.
// Prologue (s_inv fill, index math) runs BEFORE cudaGridDependencySynchronize
// so it overlaps the cumsum kernel under PDL; all g_cumsum reads come after.
// grid = (128, 4, 4) = 2048 blocks; regs capped for 7 blocks/SM (87.5% occ).
// ---------------------------------------------------------------------------
__global__ __launch_bounds__(256, 7) void span_mean_kernel(float* __restrict__ out) {
    __shared__ float s_inv[PL];

    const int tid = threadIdx.x;
    if (tid < PL) s_inv[tid] = 1.0f / (float)(tid + 1);

    const int h4 = tid & (H4 - 1);   // 0..63
    const int jj = tid >> 6;         // 0..3
    const int i0 = blockIdx.x * IG;  // 0,2,...,254
    const int b  = blockIdx.y;       // 0..3
    const int jbase = blockIdx.z * JQ;  // 0,64,128,192

    // Output base for (b, i0, j=0, h4) — pure index math, pre-sync.
    float4* __restrict__ o4 =
        (float4*)out + ((size_t)b * PL + i0) * PL * H4 + h4;
    const float4* __restrict__ c4 = (const float4*)(g_cumsum + (size_t)b * PL * PH);

    __syncthreads();                    // s_inv visible
    cudaGridDependencySynchronize();    // wait for cumsum completion (PDL)

    // Register-resident c_pad for the 2 i's this block owns.
    float4 cp[IG];
#pragma unroll
    for (int k = 0; k < IG; ++k) {
        const int i = i0 + k;
        cp[k] = (i == 0) ? make_float4(0.f, 0.f, 0.f, 0.f)
                         : c4[(size_t)(i - 1) * H4 + h4];
    }

#pragma unroll 4
    for (int j = jbase + jj; j < jbase + JQ; j += 4) {
        const float4 cj = c4[(size_t)j * H4 + h4];
#pragma unroll
        for (int k = 0; k < IG; ++k) {
            const int i = i0 + k;
            const float inv = s_inv[abs(i - j)];
            float4 v;
            v.x = (cj.x - cp[k].x) * inv;
            v.y = (cj.y - cp[k].y) * inv;
            v.z = (cj.z - cp[k].z) * inv;
            v.w = (cj.w - cp[k].w) * inv;
            __stcs(&o4[((size_t)k * PL + j) * H4], v);
        }
    }
}

// ---------------------------------------------------------------------------
extern "C" void kernel_launch(void* const* d_in, const int* in_sizes, int n_in,
                              void* d_out, int out_size) {
    const float* seq = (const float*)d_in[0];
    float* out = (float*)d_out;

    dim3 cgrid(PB, PH / 8);
    cumsum_kernel<<<cgrid, 256>>>(seq);

    // Span kernel with a PDL edge to the cumsum kernel.
    cudaLaunchConfig_t cfg = {};
    cfg.gridDim = dim3(PL / IG, PB, 4);   // (128, 4, 4) = 2048 blocks
    cfg.blockDim = dim3(256, 1, 1);
    cfg.dynamicSmemBytes = 0;
    cudaLaunchAttribute attrs[1];
    attrs[0].id = cudaLaunchAttributeProgrammaticStreamSerialization;
    attrs[0].val.programmaticStreamSerializationAllowed = 1;
    cfg.attrs = attrs;
    cfg.numAttrs = 1;
    cudaLaunchKernelEx(&cfg, span_mean_kernel, out);
}